// round 1
// baseline (speedup 1.0000x reference)
#include <cuda_runtime.h>
#include <math.h>

#define N_TOK 2048
#define DIM   2048
#define NEUR  8192
#define KSEL  32

// ---------------- scratch (static device memory; no allocations) ----------------
__device__ float g_full[(size_t)N_TOK * NEUR];   // 64 MB: silu(x @ gate^T)
__device__ float g_downT[(size_t)NEUR * DIM];    // 64 MB: down[l] transposed -> [I, D]
__device__ int   g_idx[N_TOK * KSEL];
__device__ float g_gu[N_TOK * KSEL];

// ---------------- packed f32x2 helpers ----------------
__device__ __forceinline__ unsigned long long pack2_dup(float a) {
    unsigned long long r;
    unsigned int u = __float_as_uint(a);
    asm("mov.b64 %0, {%1, %1};" : "=l"(r) : "r"(u));
    return r;
}
__device__ __forceinline__ void unpack2(unsigned long long v, float& lo, float& hi) {
    unsigned int a, b;
    asm("mov.b64 {%0, %1}, %2;" : "=r"(a), "=r"(b) : "l"(v));
    lo = __uint_as_float(a);
    hi = __uint_as_float(b);
}
__device__ __forceinline__ void ffma2(unsigned long long& d, unsigned long long a, unsigned long long b) {
    asm("fma.rn.f32x2 %0, %1, %2, %0;" : "+l"(d) : "l"(a), "l"(b));
}

__device__ __forceinline__ float silu_f(float z) {
    return z / (1.0f + expf(-z));
}

// ---------------- K1: g_full = silu(x @ gate[l]^T) ----------------
// BM=BN=128, BK=16, 256 threads, 8x8 per-thread tile, f32x2 packed FMA.
__global__ __launch_bounds__(256, 2)
void gemm_silu_kernel(const float* __restrict__ x,
                      const float* __restrict__ gate,
                      const int* __restrict__ layer_idx)
{
    __shared__ float As[16][128];
    __shared__ float Bs[16][128];

    const int l = layer_idx[0];
    const float* __restrict__ W = gate + (size_t)l * NEUR * DIM;

    const int tid = threadIdx.x;
    const int n0 = blockIdx.y * 128;   // token rows
    const int i0 = blockIdx.x * 128;   // neuron cols

    const int lr = tid >> 2;          // 0..63 : row within 64-row pass
    const int lc = (tid & 3) * 4;     // 0,4,8,12 : k offset (float4)

    const int tm = (tid >> 4) * 8;    // 0..120
    const int tn = (tid & 15) * 8;    // 0..120

    unsigned long long acc[8][4];
#pragma unroll
    for (int i = 0; i < 8; i++)
#pragma unroll
        for (int j = 0; j < 4; j++) acc[i][j] = 0ull;

    for (int d0 = 0; d0 < DIM; d0 += 16) {
#pragma unroll
        for (int p = 0; p < 2; p++) {
            int row = p * 64 + lr;
            float4 v = *reinterpret_cast<const float4*>(&x[(size_t)(n0 + row) * DIM + d0 + lc]);
            As[lc + 0][row] = v.x; As[lc + 1][row] = v.y;
            As[lc + 2][row] = v.z; As[lc + 3][row] = v.w;
            float4 w = *reinterpret_cast<const float4*>(&W[(size_t)(i0 + row) * DIM + d0 + lc]);
            Bs[lc + 0][row] = w.x; Bs[lc + 1][row] = w.y;
            Bs[lc + 2][row] = w.z; Bs[lc + 3][row] = w.w;
        }
        __syncthreads();

#pragma unroll
        for (int k = 0; k < 16; k++) {
            float4 a0 = *reinterpret_cast<const float4*>(&As[k][tm]);
            float4 a1 = *reinterpret_cast<const float4*>(&As[k][tm + 4]);
            ulonglong2 b0 = *reinterpret_cast<const ulonglong2*>(&Bs[k][tn]);
            ulonglong2 b1 = *reinterpret_cast<const ulonglong2*>(&Bs[k][tn + 4]);
            float av[8] = {a0.x, a0.y, a0.z, a0.w, a1.x, a1.y, a1.z, a1.w};
            unsigned long long bv[4] = {b0.x, b0.y, b1.x, b1.y};
#pragma unroll
            for (int i = 0; i < 8; i++) {
                unsigned long long ad = pack2_dup(av[i]);
#pragma unroll
                for (int j = 0; j < 4; j++) ffma2(acc[i][j], ad, bv[j]);
            }
        }
        __syncthreads();
    }

    // epilogue: silu + store
#pragma unroll
    for (int i = 0; i < 8; i++) {
        int n = n0 + tm + i;
        float* orow = g_full + (size_t)n * NEUR + i0 + tn;
#pragma unroll
        for (int j = 0; j < 4; j++) {
            float lo, hi;
            unpack2(acc[i][j], lo, hi);
            float2 r;
            r.x = silu_f(lo);
            r.y = silu_f(hi);
            *reinterpret_cast<float2*>(&orow[2 * j]) = r;
        }
    }
}

// ---------------- K0: downT[i][d] = down[l][d][i] ----------------
__global__ void transpose_down_kernel(const float* __restrict__ down,
                                      const int* __restrict__ layer_idx)
{
    __shared__ float t[32][33];
    const int l = layer_idx[0];
    const float* __restrict__ Dm = down + (size_t)l * DIM * NEUR;
    int i0 = blockIdx.x * 32;
    int d0 = blockIdx.y * 32;
    int tx = threadIdx.x, ty = threadIdx.y;   // block (32, 8)
#pragma unroll
    for (int r = 0; r < 32; r += 8)
        t[ty + r][tx] = Dm[(size_t)(d0 + ty + r) * NEUR + i0 + tx];
    __syncthreads();
#pragma unroll
    for (int r = 0; r < 32; r += 8)
        g_downT[(size_t)(i0 + ty + r) * DIM + d0 + tx] = t[tx][ty + r];
}

// ---------------- K2: per-row top-32 by |g_full| ----------------
__global__ __launch_bounds__(256)
void topk_kernel()
{
    __shared__ float sval[NEUR];       // 32 KB
    __shared__ float rmax[8];
    __shared__ int   rarg[8];

    const int n = blockIdx.x;
    const int tid = threadIdx.x;
    const int lane = tid & 31;
    const int wid = tid >> 5;
    const float* __restrict__ row = g_full + (size_t)n * NEUR;

    for (int i = tid; i < NEUR; i += 256) sval[i] = fabsf(row[i]);
    __syncthreads();

    for (int j = 0; j < KSEL; j++) {
        float best = -1.0f;
        int bi = NEUR;
        for (int i = tid; i < NEUR; i += 256) {
            float v = sval[i];
            if (v > best) { best = v; bi = i; }
        }
        // warp argmax (prefer lower index on exact ties)
#pragma unroll
        for (int o = 16; o; o >>= 1) {
            float ov = __shfl_down_sync(0xFFFFFFFFu, best, o);
            int   oi = __shfl_down_sync(0xFFFFFFFFu, bi, o);
            if (ov > best || (ov == best && oi < bi)) { best = ov; bi = oi; }
        }
        if (lane == 0) { rmax[wid] = best; rarg[wid] = bi; }
        __syncthreads();
        if (tid == 0) {
            float bb = rmax[0]; int bbi = rarg[0];
#pragma unroll
            for (int w = 1; w < 8; w++)
                if (rmax[w] > bb || (rmax[w] == bb && rarg[w] < bbi)) { bb = rmax[w]; bbi = rarg[w]; }
            g_idx[n * KSEL + j] = bbi;
            sval[bbi] = -1.0f;
        }
        __syncthreads();
    }
}

// ---------------- K3: gu[n][k] = g_full[n][idx] * dot(up[l][idx], x[n]) ----------------
__global__ __launch_bounds__(256)
void gu_kernel(const float* __restrict__ x,
               const float* __restrict__ up,
               const int* __restrict__ layer_idx)
{
    __shared__ float xs[DIM];     // 8 KB
    __shared__ float red[8];

    const int n = blockIdx.x;
    const int tid = threadIdx.x;
    const int lane = tid & 31;
    const int wid = tid >> 5;
    const int l = layer_idx[0];
    const float* __restrict__ U = up + (size_t)l * NEUR * DIM;

    const float* __restrict__ xr = x + (size_t)n * DIM;
    for (int i = tid; i < DIM; i += 256) xs[i] = xr[i];
    __syncthreads();

    for (int k = 0; k < KSEL; k++) {
        int id = g_idx[n * KSEL + k];
        const float* __restrict__ ur = U + (size_t)id * DIM;
        float s = 0.0f;
        for (int i = tid; i < DIM; i += 256) s += ur[i] * xs[i];
#pragma unroll
        for (int o = 16; o; o >>= 1) s += __shfl_down_sync(0xFFFFFFFFu, s, o);
        if (lane == 0) red[wid] = s;
        __syncthreads();
        if (tid == 0) {
            float t = 0.0f;
#pragma unroll
            for (int w = 0; w < 8; w++) t += red[w];
            g_gu[n * KSEL + k] = g_full[(size_t)n * NEUR + id] * t;
        }
        __syncthreads();
    }
}

// ---------------- K4: out[n][d] = sum_k gu[n][k] * downT[idx[n][k]][d] ----------------
__global__ __launch_bounds__(256)
void down_kernel(float* __restrict__ out)
{
    __shared__ int   sidx[KSEL];
    __shared__ float sgu[KSEL];

    const int n = blockIdx.x;
    const int tid = threadIdx.x;
    if (tid < KSEL) {
        sidx[tid] = g_idx[n * KSEL + tid];
        sgu[tid] = g_gu[n * KSEL + tid];
    }
    __syncthreads();

    float acc[8];
#pragma unroll
    for (int j = 0; j < 8; j++) acc[j] = 0.0f;

    for (int k = 0; k < KSEL; k++) {
        const float* __restrict__ dr = g_downT + (size_t)sidx[k] * DIM;
        float w = sgu[k];
#pragma unroll
        for (int j = 0; j < 8; j++) acc[j] += w * dr[tid + j * 256];
    }
#pragma unroll
    for (int j = 0; j < 8; j++) out[(size_t)n * DIM + tid + j * 256] = acc[j];
}

// ---------------- launch ----------------
extern "C" void kernel_launch(void* const* d_in, const int* in_sizes, int n_in,
                              void* d_out, int out_size)
{
    const float* x     = (const float*)d_in[0];
    const float* gate  = (const float*)d_in[1];
    const float* up    = (const float*)d_in[2];
    const float* down  = (const float*)d_in[3];
    const int*   lidx  = (const int*)d_in[4];
    float* out = (float*)d_out;

    dim3 gg(NEUR / 128, N_TOK / 128);
    gemm_silu_kernel<<<gg, 256>>>(x, gate, lidx);
    transpose_down_kernel<<<dim3(NEUR / 32, DIM / 32), dim3(32, 8)>>>(down, lidx);
    topk_kernel<<<N_TOK, 256>>>();
    gu_kernel<<<N_TOK, 256>>>(x, up, lidx);
    down_kernel<<<N_TOK, 256>>>(out);
}

// round 5
// speedup vs baseline: 3.2119x; 3.2119x over previous
#include <cuda_runtime.h>
#include <cuda_bf16.h>
#include <math.h>

#define N_TOK 2048
#define DIM   2048
#define NEUR  8192
#define KSEL  32
#define CAND_CAP 192
#define MINC  36
#define NBIN  8192   // bin = key >> 3

// ---------------- static scratch ----------------
__device__ __nv_bfloat16 g_xbf[(size_t)N_TOK * DIM];     // 8 MB
__device__ __nv_bfloat16 g_gbf[(size_t)NEUR * DIM];      // 32 MB
__device__ unsigned short g_scores[(size_t)N_TOK * NEUR];// 32 MB (bf16 bits of |silu|)
__device__ float g_downT[(size_t)NEUR * DIM];            // 64 MB
__device__ int   g_cand[N_TOK * CAND_CAP];
__device__ int   g_ccnt[N_TOK];
__device__ int   g_idx[N_TOK * KSEL];
__device__ float g_gsel[N_TOK * KSEL];
__device__ float g_gu[N_TOK * KSEL];

__device__ __forceinline__ float silu_exact(float z) { return z / (1.0f + expf(-z)); }
__device__ __forceinline__ float silu_fast(float z)  { return z / (1.0f + __expf(-z)); }

// ---------------- conversions ----------------
__global__ void conv_x_kernel(const float* __restrict__ x) {
    int i = blockIdx.x * blockDim.x + threadIdx.x;     // one float4
    const float4* src = reinterpret_cast<const float4*>(x);
    float4 v = src[i];
    __nv_bfloat162* dst = reinterpret_cast<__nv_bfloat162*>(g_xbf);
    dst[2 * i + 0] = __float22bfloat162_rn(make_float2(v.x, v.y));
    dst[2 * i + 1] = __float22bfloat162_rn(make_float2(v.z, v.w));
}
__global__ void conv_gate_kernel(const float* __restrict__ gate, const int* __restrict__ lidx) {
    const float* g = gate + (size_t)lidx[0] * NEUR * DIM;
    int i = blockIdx.x * blockDim.x + threadIdx.x;
    const float4* src = reinterpret_cast<const float4*>(g);
    float4 v = src[i];
    __nv_bfloat162* dst = reinterpret_cast<__nv_bfloat162*>(g_gbf);
    dst[2 * i + 0] = __float22bfloat162_rn(make_float2(v.x, v.y));
    dst[2 * i + 1] = __float22bfloat162_rn(make_float2(v.z, v.w));
}

// ---------------- K0: down transpose ----------------
__global__ void transpose_down_kernel(const float* __restrict__ down,
                                      const int* __restrict__ lidx) {
    __shared__ float t[32][33];
    const float* Dm = down + (size_t)lidx[0] * DIM * NEUR;
    int i0 = blockIdx.x * 32, d0 = blockIdx.y * 32;
    int tx = threadIdx.x, ty = threadIdx.y;
#pragma unroll
    for (int r = 0; r < 32; r += 8)
        t[ty + r][tx] = Dm[(size_t)(d0 + ty + r) * NEUR + i0 + tx];
    __syncthreads();
#pragma unroll
    for (int r = 0; r < 32; r += 8)
        g_downT[(size_t)(i0 + ty + r) * DIM + d0 + tx] = t[tx][ty + r];
}

// ---------------- K1: bf16 tensor-core GEMM -> |silu| scores ----------------
#define BM 128
#define BN 128
#define BK 32
#define PITCH 40   // bf16 elems per smem row (80B: conflict-free ldmatrix)

__device__ __forceinline__ void cpasync16(void* smem, const void* g) {
    unsigned saddr = (unsigned)__cvta_generic_to_shared(smem);
    asm volatile("cp.async.cg.shared.global [%0], [%1], 16;\n" :: "r"(saddr), "l"(g));
}
__device__ __forceinline__ void ldm_x4(unsigned& r0, unsigned& r1, unsigned& r2, unsigned& r3,
                                       const void* smem) {
    unsigned saddr = (unsigned)__cvta_generic_to_shared(smem);
    asm volatile("ldmatrix.sync.aligned.m8n8.x4.shared.b16 {%0,%1,%2,%3}, [%4];\n"
                 : "=r"(r0), "=r"(r1), "=r"(r2), "=r"(r3) : "r"(saddr));
}
__device__ __forceinline__ void mma_bf16(float* c, const unsigned* a, const unsigned* b) {
    asm volatile("mma.sync.aligned.m16n8k16.row.col.f32.bf16.bf16.f32 "
                 "{%0,%1,%2,%3}, {%4,%5,%6,%7}, {%8,%9}, {%0,%1,%2,%3};\n"
                 : "+f"(c[0]), "+f"(c[1]), "+f"(c[2]), "+f"(c[3])
                 : "r"(a[0]), "r"(a[1]), "r"(a[2]), "r"(a[3]), "r"(b[0]), "r"(b[1]));
}

__global__ __launch_bounds__(256)
void gemm_score_kernel() {
    __shared__ __nv_bfloat16 As[2][BM * PITCH];
    __shared__ __nv_bfloat16 Bs[2][BM * PITCH];

    const int tid = threadIdx.x, wid = tid >> 5, lane = tid & 31;
    const int n0 = blockIdx.y * BM;
    const int i0 = blockIdx.x * BN;
    const int wm = (wid >> 2) * 64;
    const int wn = (wid & 3) * 32;

    const int a_row = lane & 15;
    const int a_kk  = (lane >> 4) * 8;
    const int b_row = (lane & 7) + ((lane >> 4) << 3);
    const int b_kk  = ((lane >> 3) & 1) * 8;

    float acc[4][4][4];
#pragma unroll
    for (int m = 0; m < 4; m++)
#pragma unroll
        for (int n = 0; n < 4; n++)
#pragma unroll
            for (int j = 0; j < 4; j++) acc[m][n][j] = 0.0f;

    const int NITER = DIM / BK;

    {
        int k0 = 0, buf = 0;
#pragma unroll
        for (int h = 0; h < 2; h++) {
            int c = tid + h * 256;
            int row = c >> 2, kc = (c & 3) * 8;
            cpasync16(&As[buf][row * PITCH + kc], g_xbf + (size_t)(n0 + row) * DIM + k0 + kc);
            cpasync16(&Bs[buf][row * PITCH + kc], g_gbf + (size_t)(i0 + row) * DIM + k0 + kc);
        }
        asm volatile("cp.async.commit_group;\n");
    }

    for (int it = 0; it < NITER; it++) {
        if (it + 1 < NITER) {
            int k0 = (it + 1) * BK, buf = (it + 1) & 1;
#pragma unroll
            for (int h = 0; h < 2; h++) {
                int c = tid + h * 256;
                int row = c >> 2, kc = (c & 3) * 8;
                cpasync16(&As[buf][row * PITCH + kc], g_xbf + (size_t)(n0 + row) * DIM + k0 + kc);
                cpasync16(&Bs[buf][row * PITCH + kc], g_gbf + (size_t)(i0 + row) * DIM + k0 + kc);
            }
            asm volatile("cp.async.commit_group;\n");
            asm volatile("cp.async.wait_group 1;\n");
        } else {
            asm volatile("cp.async.wait_group 0;\n");
        }
        __syncthreads();

        const __nv_bfloat16* Ab = As[it & 1];
        const __nv_bfloat16* Bb = Bs[it & 1];
#pragma unroll
        for (int ks = 0; ks < 2; ks++) {
            unsigned a[4][4], b[4][2];
#pragma unroll
            for (int mt = 0; mt < 4; mt++)
                ldm_x4(a[mt][0], a[mt][1], a[mt][2], a[mt][3],
                       Ab + (wm + mt * 16 + a_row) * PITCH + ks * 16 + a_kk);
#pragma unroll
            for (int bt = 0; bt < 2; bt++) {
                unsigned r0, r1, r2, r3;
                ldm_x4(r0, r1, r2, r3,
                       Bb + (wn + bt * 16 + b_row) * PITCH + ks * 16 + b_kk);
                b[bt * 2 + 0][0] = r0; b[bt * 2 + 0][1] = r1;
                b[bt * 2 + 1][0] = r2; b[bt * 2 + 1][1] = r3;
            }
#pragma unroll
            for (int mt = 0; mt < 4; mt++)
#pragma unroll
                for (int nt = 0; nt < 4; nt++)
                    mma_bf16(acc[mt][nt], a[mt], b[nt]);
        }
        __syncthreads();
    }

#pragma unroll
    for (int mt = 0; mt < 4; mt++) {
#pragma unroll
        for (int nt = 0; nt < 4; nt++) {
            int row = n0 + wm + mt * 16 + (lane >> 2);
            int col = i0 + wn + nt * 8 + (lane & 3) * 2;
            float s0 = fabsf(silu_fast(acc[mt][nt][0]));
            float s1 = fabsf(silu_fast(acc[mt][nt][1]));
            float s2 = fabsf(silu_fast(acc[mt][nt][2]));
            float s3 = fabsf(silu_fast(acc[mt][nt][3]));
            __nv_bfloat162* o0 = reinterpret_cast<__nv_bfloat162*>(
                g_scores + (size_t)row * NEUR + col);
            __nv_bfloat162* o1 = reinterpret_cast<__nv_bfloat162*>(
                g_scores + (size_t)(row + 8) * NEUR + col);
            *o0 = __float22bfloat162_rn(make_float2(s0, s1));
            *o1 = __float22bfloat162_rn(make_float2(s2, s3));
        }
    }
}

// ---------------- K2: candidate selection via fine histogram ----------------
// smem: 32KB hist + 1KB csum (fits 48KB static limit; score row re-read hits L2)
__global__ __launch_bounds__(256)
void cand_kernel() {
    __shared__ unsigned hist[NBIN];         // 32 KB (bin = key >> 3)
    __shared__ unsigned csum[256];
    __shared__ int s_floor;
    __shared__ int s_cnt;

    const int n = blockIdx.x;
    const int tid = threadIdx.x;
    const unsigned short* row = g_scores + (size_t)n * NEUR;

    for (int i = tid; i < NBIN; i += 256) hist[i] = 0;
    if (tid == 0) s_cnt = 0;
    __syncthreads();

    // pass 1: histogram (vectorized read, 4 keys per thread-iter)
    const ushort4* row4 = reinterpret_cast<const ushort4*>(row);
    for (int i = tid; i < NEUR / 4; i += 256) {
        ushort4 k = row4[i];
        atomicAdd(&hist[k.x >> 3], 1u);
        atomicAdd(&hist[k.y >> 3], 1u);
        atomicAdd(&hist[k.z >> 3], 1u);
        atomicAdd(&hist[k.w >> 3], 1u);
    }
    __syncthreads();

    // per-thread chunk of 32 bins
    const int CPB = NBIN / 256;   // 32
    unsigned local = 0;
#pragma unroll
    for (int j = 0; j < CPB; j++) local += hist[tid * CPB + j];
    csum[tid] = local;
    __syncthreads();

    unsigned above = 0;
    for (int u = tid + 1; u < 256; u++) above += csum[u];
    if (above < MINC && above + local >= MINC) {
        unsigned acc = above;
        for (int j = CPB - 1; j >= 0; j--) {
            acc += hist[tid * CPB + j];
            if (acc >= MINC) { s_floor = (tid * CPB + j) << 3; break; }
        }
    }
    __syncthreads();

    // pass 2: collect indices >= floor (row re-read: L2 hit)
    unsigned short floor_key = (unsigned short)s_floor;
    for (int i = tid; i < NEUR / 4; i += 256) {
        ushort4 k = row4[i];
        int base = i * 4;
        if (k.x >= floor_key) { int p = atomicAdd(&s_cnt, 1); if (p < CAND_CAP) g_cand[n * CAND_CAP + p] = base + 0; }
        if (k.y >= floor_key) { int p = atomicAdd(&s_cnt, 1); if (p < CAND_CAP) g_cand[n * CAND_CAP + p] = base + 1; }
        if (k.z >= floor_key) { int p = atomicAdd(&s_cnt, 1); if (p < CAND_CAP) g_cand[n * CAND_CAP + p] = base + 2; }
        if (k.w >= floor_key) { int p = atomicAdd(&s_cnt, 1); if (p < CAND_CAP) g_cand[n * CAND_CAP + p] = base + 3; }
    }
    __syncthreads();
    if (tid == 0) g_ccnt[n] = s_cnt < CAND_CAP ? s_cnt : CAND_CAP;
}

// ---------------- K3: exact fp32 rerank -> top-32 + g_sel ----------------
__global__ __launch_bounds__(256)
void rerank_kernel(const float* __restrict__ x,
                   const float* __restrict__ gate,
                   const int* __restrict__ lidx) {
    __shared__ float xs[DIM];      // 8 KB
    __shared__ float sg[CAND_CAP];
    __shared__ float sabs[CAND_CAP];
    __shared__ int   sid[CAND_CAP];

    const int n = blockIdx.x;
    const int tid = threadIdx.x, wid = tid >> 5, lane = tid & 31;
    const float* W = gate + (size_t)lidx[0] * NEUR * DIM;

    const float4* xr = reinterpret_cast<const float4*>(x + (size_t)n * DIM);
    float4* xs4 = reinterpret_cast<float4*>(xs);
    for (int i = tid; i < DIM / 4; i += 256) xs4[i] = xr[i];
    if (tid < CAND_CAP) sabs[tid] = -1.0f;
    __syncthreads();

    const int c = g_ccnt[n];
    for (int ci = wid; ci < c; ci += 8) {
        int id = g_cand[n * CAND_CAP + ci];
        const float4* wr = reinterpret_cast<const float4*>(W + (size_t)id * DIM);
        float s = 0.0f;
#pragma unroll
        for (int j = 0; j < 16; j++) {
            float4 wv = wr[lane + 32 * j];
            float4 xv = xs4[lane + 32 * j];
            s += wv.x * xv.x + wv.y * xv.y + wv.z * xv.z + wv.w * xv.w;
        }
#pragma unroll
        for (int o = 16; o; o >>= 1) s += __shfl_down_sync(0xFFFFFFFFu, s, o);
        if (lane == 0) {
            float g = silu_exact(s);
            sg[ci] = g; sabs[ci] = fabsf(g); sid[ci] = id;
        }
    }
    __syncthreads();

    if (wid == 0) {
        for (int k = 0; k < KSEL; k++) {
            float best = -2.0f; int bi = 1 << 20;
#pragma unroll
            for (int sft = 0; sft < CAND_CAP / 32; sft++) {
                int ci = lane + 32 * sft;
                float v = sabs[ci];
                if (v > best || (v == best && ci < bi)) { best = v; bi = ci; }
            }
#pragma unroll
            for (int o = 16; o; o >>= 1) {
                float ov = __shfl_down_sync(0xFFFFFFFFu, best, o);
                int   oi = __shfl_down_sync(0xFFFFFFFFu, bi, o);
                if (ov > best || (ov == best && oi < bi)) { best = ov; bi = oi; }
            }
            bi = __shfl_sync(0xFFFFFFFFu, bi, 0);
            if (lane == 0) {
                g_idx[n * KSEL + k] = sid[bi];
                g_gsel[n * KSEL + k] = sg[bi];
            }
            sabs[bi] = -2.0f;   // all lanes write same value; benign
            __syncwarp();
        }
    }
}

// ---------------- K4: up dots -> gu ----------------
__global__ __launch_bounds__(256)
void up_kernel(const float* __restrict__ x,
               const float* __restrict__ up,
               const int* __restrict__ lidx) {
    __shared__ float xs[DIM];
    const int n = blockIdx.x;
    const int tid = threadIdx.x, wid = tid >> 5, lane = tid & 31;
    const float* U = up + (size_t)lidx[0] * NEUR * DIM;

    const float4* xr = reinterpret_cast<const float4*>(x + (size_t)n * DIM);
    float4* xs4 = reinterpret_cast<float4*>(xs);
    for (int i = tid; i < DIM / 4; i += 256) xs4[i] = xr[i];
    __syncthreads();

    for (int k = wid; k < KSEL; k += 8) {
        int id = g_idx[n * KSEL + k];
        const float4* ur = reinterpret_cast<const float4*>(U + (size_t)id * DIM);
        float s = 0.0f;
#pragma unroll
        for (int j = 0; j < 16; j++) {
            float4 uv = ur[lane + 32 * j];
            float4 xv = xs4[lane + 32 * j];
            s += uv.x * xv.x + uv.y * xv.y + uv.z * xv.z + uv.w * xv.w;
        }
#pragma unroll
        for (int o = 16; o; o >>= 1) s += __shfl_down_sync(0xFFFFFFFFu, s, o);
        if (lane == 0) g_gu[n * KSEL + k] = g_gsel[n * KSEL + k] * s;
    }
}

// ---------------- K5: down accumulation ----------------
__global__ __launch_bounds__(256)
void down_kernel(float* __restrict__ out) {
    __shared__ int   sidx[KSEL];
    __shared__ float sgu[KSEL];
    const int n = blockIdx.x;
    const int tid = threadIdx.x;
    if (tid < KSEL) {
        sidx[tid] = g_idx[n * KSEL + tid];
        sgu[tid] = g_gu[n * KSEL + tid];
    }
    __syncthreads();

    float acc[8];
#pragma unroll
    for (int j = 0; j < 8; j++) acc[j] = 0.0f;
    for (int k = 0; k < KSEL; k++) {
        const float* dr = g_downT + (size_t)sidx[k] * DIM;
        float w = sgu[k];
#pragma unroll
        for (int j = 0; j < 8; j++) acc[j] += w * dr[tid + j * 256];
    }
#pragma unroll
    for (int j = 0; j < 8; j++) out[(size_t)n * DIM + tid + j * 256] = acc[j];
}

// ---------------- launch ----------------
extern "C" void kernel_launch(void* const* d_in, const int* in_sizes, int n_in,
                              void* d_out, int out_size) {
    const float* x    = (const float*)d_in[0];
    const float* gate = (const float*)d_in[1];
    const float* up   = (const float*)d_in[2];
    const float* down = (const float*)d_in[3];
    const int*   lidx = (const int*)d_in[4];
    float* out = (float*)d_out;

    conv_x_kernel<<<(N_TOK * DIM / 4) / 256, 256>>>(x);
    conv_gate_kernel<<<(NEUR * DIM / 4) / 256, 256>>>(gate, lidx);
    transpose_down_kernel<<<dim3(NEUR / 32, DIM / 32), dim3(32, 8)>>>(down, lidx);

    gemm_score_kernel<<<dim3(NEUR / BN, N_TOK / BM), 256>>>();
    cand_kernel<<<N_TOK, 256>>>();
    rerank_kernel<<<N_TOK, 256>>>(x, gate, lidx);
    up_kernel<<<N_TOK, 256>>>(x, up, lidx);
    down_kernel<<<N_TOK, 256>>>(out);
}